// round 15
// baseline (speedup 1.0000x reference)
#include <cuda_runtime.h>
#include <cuda_fp16.h>
#include <cstdint>

#define C2    2048
#define NPIX  4096
#define BATCH 2

typedef __half fp16;

// ---------------------------------------------------------------------------
// Static device scratch (no allocations anywhere)
// ---------------------------------------------------------------------------
__device__ fp16 g_Xt_h[(size_t)BATCH * NPIX * 2 * C2];   // [b][pix][4096 ch]
__device__ fp16 g_wqk_h[(size_t)2 * C2 * 2 * C2];        // [wq;wk] fused
__device__ fp16 g_wv2_h[(size_t)C2 * 2 * C2];            // folded V weights
__device__ float g_bqk[2 * C2];                          // [bq;bk]
__device__ float g_bv2[C2];
__device__ fp16 g_QKt_h[(size_t)BATCH * NPIX * 2 * C2];  // [b][pix][Q 0..2047|K 2048..4095]
__device__ fp16 g_V2_h[(size_t)BATCH * C2 * NPIX];       // [b][ch][pix]
__device__ fp16 g_At_h[(size_t)BATCH * NPIX * NPIX];     // attn fp16

// ---------------------------------------------------------------------------
// helpers
// ---------------------------------------------------------------------------
__device__ __forceinline__ uint32_t smem_u32(const void* p) {
    uint32_t a;
    asm("{ .reg .u64 t; cvta.to.shared.u64 t, %1; cvt.u32.u64 %0, t; }"
        : "=r"(a) : "l"(p));
    return a;
}
__device__ __forceinline__ uint32_t swz(uint32_t b) {       // 128B-row swizzle
    return b ^ ((b >> 3) & 0x70);
}
__device__ __forceinline__ void cp_async16(uint32_t dst, const void* src) {
    asm volatile("cp.async.cg.shared.global [%0], [%1], 16;\n"
                 :: "r"(dst), "l"(src) : "memory");
}
__device__ __forceinline__ void ldsm_x4(uint32_t* r, uint32_t addr) {
    asm volatile("ldmatrix.sync.aligned.m8n8.x4.shared.b16 {%0,%1,%2,%3}, [%4];"
                 : "=r"(r[0]), "=r"(r[1]), "=r"(r[2]), "=r"(r[3]) : "r"(addr));
}
__device__ __forceinline__ void mma16816(float* d, const uint32_t* a,
                                         const uint32_t* b) {
    asm volatile(
        "mma.sync.aligned.m16n8k16.row.col.f32.f16.f16.f32 "
        "{%0,%1,%2,%3}, {%4,%5,%6,%7}, {%8,%9}, {%0,%1,%2,%3};"
        : "+f"(d[0]), "+f"(d[1]), "+f"(d[2]), "+f"(d[3])
        : "r"(a[0]), "r"(a[1]), "r"(a[2]), "r"(a[3]), "r"(b[0]), "r"(b[1]));
}

// ---------------------------------------------------------------------------
// Pack + transpose: f_rgb/f_i -> fp32 output copies and Xt (fp16)
// ---------------------------------------------------------------------------
__global__ void pack_transpose_kernel(const float* __restrict__ frgb,
                                      const float* __restrict__ fi,
                                      float* __restrict__ out)
{
    __shared__ float tile[32][33];
    const int s = blockIdx.z & 1, b = blockIdx.z >> 1;
    const float* src = s ? fi : frgb;
    const int pix0 = blockIdx.x * 32, ch0 = blockIdx.y * 32;
    const size_t base = (size_t)b * C2 * NPIX;
    const size_t PER  = (size_t)BATCH * C2 * NPIX;
    const int tx = threadIdx.x, ty = threadIdx.y;
#pragma unroll
    for (int i = 0; i < 4; ++i) {
        const int ch = ch0 + ty + i * 8;
        const size_t idx = base + (size_t)ch * NPIX + pix0 + tx;
        float v = src[idx];
        out[PER * (1 + s) + idx] = v;          // f_rgb / f_i copy
        tile[ty + i * 8][tx] = v;
    }
    __syncthreads();
    const size_t xbase = (size_t)b * NPIX * (2 * C2) + (size_t)s * C2;
#pragma unroll
    for (int i = 0; i < 4; ++i) {
        const int pix = pix0 + ty + i * 8;
        float v = tile[tx][ty + i * 8];
        const size_t idx = xbase + (size_t)pix * (2 * C2) + ch0 + tx;
        g_Xt_h[idx] = __float2half_rn(v);
    }
}

// ---------------------------------------------------------------------------
// Weight prep: fused [wq;wk], fold wv, biases
// ---------------------------------------------------------------------------
__global__ void weights_prep_kernel(const float* __restrict__ wq,
                                    const float* __restrict__ wk,
                                    const float* __restrict__ wv,
                                    const float* __restrict__ bq,
                                    const float* __restrict__ bk,
                                    const float* __restrict__ bv)
{
    const size_t NW = (size_t)C2 * 2 * C2;
    size_t i = (size_t)blockIdx.x * blockDim.x + threadIdx.x;
    if (i < NW) {
        g_wqk_h[i]      = __float2half_rn(wq[i]);
        g_wqk_h[NW + i] = __float2half_rn(wk[i]);
        g_wv2_h[i]      = __float2half_rn(wv[i] + wv[i + NW]);
    }
    if (i < C2) {
        g_bqk[i]      = bq[i];
        g_bqk[C2 + i] = bk[i];
        g_bv2[i]      = bv[i] + bv[i + C2];
    }
}

// ---------------------------------------------------------------------------
// HMMA GEMM:  D[M,N] = alpha * A[M,K] @ B[N,K]^T (+bias)
// CTA tile 128x256, kTile 64, 8 warps (warp tile 64x64),
// 4-slot cp.async ring (48KB/stage, 192KB smem) with wait_group 2,
// 1 CTA/SM. Pass-ordered 32-MMA streams (all distinct accumulators).
// MODE 0: out fp16 row-major (+bias); MODE 1: out f32 row-major * alpha.
// ---------------------------------------------------------------------------
static constexpr int TILE_A    = 16384;          // 128x64 fp16
static constexpr int TILE_B    = 32768;          // 256x64 fp16
static constexpr int STAGE_B   = TILE_A + TILE_B;  // 48KB
static constexpr int GEMM_SMEM = 4 * STAGE_B + 128;

template<int MODE>
__global__ void __launch_bounds__(256, 1)
hgemm(const fp16* __restrict__ Ah, const fp16* __restrict__ Bh,
      size_t sAb, size_t sBb, int lda, int ldb, int K,
      void* __restrict__ out0v,
      int ldo, size_t sOb, float alpha,
      const float* __restrict__ bias_m, const float* __restrict__ bias_n)
{
    extern __shared__ __align__(128) char dsm[];
    const uint32_t smbase = (smem_u32(dsm) + 127u) & ~127u;

    const int tid  = threadIdx.x;
    const int lane = tid & 31, warp = tid >> 5;
    const int m0 = blockIdx.y * 128;
    const int n0 = blockIdx.x * 256;
    const int b  = blockIdx.z;
    Ah += sAb * b;
    Bh += sBb * b;

    const int wm = (warp >> 2) * 64;     // warp M offset (2 in M)
    const int wn = (warp & 3) * 64;      // warp N offset (4 in N)
    const int kcrot = (warp >> 2) * 2;   // kc phase stagger per SMSP pair

    float acc[4][8][4];
#pragma unroll
    for (int i = 0; i < 4; ++i)
#pragma unroll
        for (int j = 0; j < 8; ++j)
#pragma unroll
            for (int q = 0; q < 4; ++q) acc[i][j][q] = 0.f;

    // ---- hoisted ldmatrix addressing ----
    const int arow = wm + (lane & 15);
    const int brow = wn + (lane & 15);
    const uint32_t hk  = (uint32_t)(lane >> 4);
    const uint32_t sxa = (uint32_t)(arow & 7);
    const uint32_t sxb = (uint32_t)(brow & 7);
    uint32_t colA[4], colB[4], aoff[4], boff[4];
#pragma unroll
    for (int kc = 0; kc < 4; ++kc) {
        const uint32_t kce = (uint32_t)((kc + kcrot) & 3);
        colA[kc] = (((kce * 2) + hk) ^ sxa) << 4;
        colB[kc] = (((kce * 2) + hk) ^ sxb) << 4;
    }
#pragma unroll
    for (int mi = 0; mi < 4; ++mi) aoff[mi] = (uint32_t)((arow + mi * 16) * 128);
#pragma unroll
    for (int g = 0; g < 4; ++g)    boff[g] = (uint32_t)((brow + g * 16) * 128);

    // ---- hoisted cp.async addressing ----
    const int r0t = tid >> 3;                         // row 0..31 (first chunk)
    const int c8  = (tid & 7) * 8;                    // fp16 col of 16B chunk
    const size_t gA0 = (size_t)(m0 + r0t) * lda + c8;
    const size_t gB0 = (size_t)(n0 + r0t) * ldb + c8;
    const size_t gstepA = (size_t)32 * lda;           // +32 rows per chunk
    const size_t gstepB = (size_t)32 * ldb;
    const uint32_t soff0 = swz((uint32_t)(r0t * 128 + (tid & 7) * 16));

    const int NK = K / 64;

    auto load_stage = [&](int kt, int slot) {
        if (kt < NK) {
            const uint32_t sb = smbase + (uint32_t)slot * STAGE_B;
            const int k0 = kt * 64;
            const fp16* pAh = Ah + gA0 + k0;
            const fp16* pBh = Bh + gB0 + k0;
#pragma unroll
            for (int j = 0; j < 4; ++j)               // A: 128 rows
                cp_async16(sb + soff0 + (uint32_t)(j * 4096),
                           pAh + (size_t)j * gstepA);
#pragma unroll
            for (int j = 0; j < 8; ++j)               // B: 256 rows
                cp_async16(sb + TILE_A + soff0 + (uint32_t)(j * 4096),
                           pBh + (size_t)j * gstepB);
        }
        asm volatile("cp.async.commit_group;" ::: "memory");
    };

    load_stage(0, 0);
    load_stage(1, 1);
    load_stage(2, 2);
    int cur = 0, wr = 3;

    for (int kt = 0; kt < NK; ++kt) {
        asm volatile("cp.async.wait_group 2;" ::: "memory");
        __syncthreads();
        load_stage(kt + 3, wr);
        wr = (wr + 1) & 3;

        const uint32_t sb = smbase + (uint32_t)cur * STAGE_B;
        cur = (cur + 1) & 3;
        const uint32_t aH = sb;
        const uint32_t bH = sb + TILE_A;

#pragma unroll
        for (int kc = 0; kc < 4; ++kc) {
            const uint32_t cA = colA[kc], cB = colB[kc];
            uint32_t a1[4][4], b1[8][2], t[4];

#pragma unroll
            for (int mi = 0; mi < 4; ++mi)
                ldsm_x4(a1[mi], aH + aoff[mi] + cA);
#pragma unroll
            for (int g = 0; g < 4; ++g) {
                ldsm_x4(t, bH + boff[g] + cB);
                b1[2 * g][0]     = t[0]; b1[2 * g][1]     = t[2];
                b1[2 * g + 1][0] = t[1]; b1[2 * g + 1][1] = t[3];
            }
#pragma unroll
            for (int mi = 0; mi < 4; ++mi)
#pragma unroll
                for (int ni = 0; ni < 8; ++ni)
                    mma16816(acc[mi][ni], a1[mi], b1[ni]);
        }
    }

    // ------------------------------- epilogue ------------------------------
    const int r0 = m0 + wm + (lane >> 2);
    const int c0 = n0 + wn + (lane & 3) * 2;
#pragma unroll
    for (int mi = 0; mi < 4; ++mi) {
        const int rA = r0 + mi * 16, rB = rA + 8;
        float bmA = 0.f, bmB = 0.f;
        if (MODE == 0 && bias_m) { bmA = bias_m[rA]; bmB = bias_m[rB]; }
#pragma unroll
        for (int ni = 0; ni < 8; ++ni) {
            const int col = c0 + ni * 8;
            if (MODE == 1) {
                float* o = (float*)out0v + sOb * b;
                float2 u;
                u.x = acc[mi][ni][0] * alpha; u.y = acc[mi][ni][1] * alpha;
                *(float2*)(o + (size_t)rA * ldo + col) = u;
                u.x = acc[mi][ni][2] * alpha; u.y = acc[mi][ni][3] * alpha;
                *(float2*)(o + (size_t)rB * ldo + col) = u;
            } else {
                fp16* oh = (fp16*)out0v + sOb * b;
                float bn0 = 0.f, bn1 = 0.f;
                if (bias_n) { bn0 = bias_n[col]; bn1 = bias_n[col + 1]; }
                float v0 = acc[mi][ni][0] + bmA + bn0;
                float v1 = acc[mi][ni][1] + bmA + bn1;
                float v2 = acc[mi][ni][2] + bmB + bn0;
                float v3 = acc[mi][ni][3] + bmB + bn1;
                *(__half2*)(oh + (size_t)rA * ldo + col) =
                    __halves2half2(__float2half_rn(v0), __float2half_rn(v1));
                *(__half2*)(oh + (size_t)rB * ldo + col) =
                    __halves2half2(__float2half_rn(v2), __float2half_rn(v3));
            }
        }
    }
}

// ---------------------------------------------------------------------------
// Row softmax: f32 in/out on attn, plus fp16 for the final GEMM
// ---------------------------------------------------------------------------
__global__ void softmax_kernel(float* __restrict__ attn,
                               fp16* __restrict__ ah)
{
    const size_t roff = (size_t)blockIdx.x * NPIX;
    float* p = attn + roff;
    const int t = threadIdx.x;
    float v[16];
    float mx = -1e30f;
#pragma unroll
    for (int j = 0; j < 16; ++j) {
        v[j] = p[t + 256 * j];
        mx = fmaxf(mx, v[j]);
    }
    __shared__ float sred[8];
#pragma unroll
    for (int o = 16; o; o >>= 1)
        mx = fmaxf(mx, __shfl_xor_sync(0xffffffffu, mx, o));
    if ((t & 31) == 0) sred[t >> 5] = mx;
    __syncthreads();
    mx = sred[0];
#pragma unroll
    for (int k = 1; k < 8; ++k) mx = fmaxf(mx, sred[k]);

    float s = 0.f;
#pragma unroll
    for (int j = 0; j < 16; ++j) {
        v[j] = __expf(v[j] - mx);
        s += v[j];
    }
#pragma unroll
    for (int o = 16; o; o >>= 1)
        s += __shfl_xor_sync(0xffffffffu, s, o);
    __syncthreads();
    if ((t & 31) == 0) sred[t >> 5] = s;
    __syncthreads();
    s = 0.f;
#pragma unroll
    for (int k = 0; k < 8; ++k) s += sred[k];

    const float inv = 1.f / s;
#pragma unroll
    for (int j = 0; j < 16; ++j) {
        const int idx = t + 256 * j;
        float o = v[j] * inv;
        p[idx] = o;
        ah[roff + idx] = __float2half_rn(o);
    }
}

// ---------------------------------------------------------------------------
// kernel_launch (single stream — graph-capture safe)
// Inputs: f_rgb, f_i, wq, bq, wk, bk, wv, bv
// Output: [f_final | f_rgb | f_i | attn] fp32
// ---------------------------------------------------------------------------
extern "C" void kernel_launch(void* const* d_in, const int* in_sizes, int n_in,
                              void* d_out, int out_size)
{
    const float* f_rgb = (const float*)d_in[0];
    const float* f_i   = (const float*)d_in[1];
    const float* wq    = (const float*)d_in[2];
    const float* bq    = (const float*)d_in[3];
    const float* wk    = (const float*)d_in[4];
    const float* bk    = (const float*)d_in[5];
    const float* wv    = (const float*)d_in[6];
    const float* bv    = (const float*)d_in[7];
    float* out = (float*)d_out;

    cudaFuncSetAttribute(hgemm<0>, cudaFuncAttributeMaxDynamicSharedMemorySize, GEMM_SMEM);
    cudaFuncSetAttribute(hgemm<1>, cudaFuncAttributeMaxDynamicSharedMemorySize, GEMM_SMEM);

    fp16 *Xh, *qkh, *vh;
    fp16 *QKh, *Vh, *Ath;
    float *bqk, *bv2;
    cudaGetSymbolAddress((void**)&Xh,  g_Xt_h);
    cudaGetSymbolAddress((void**)&qkh, g_wqk_h);
    cudaGetSymbolAddress((void**)&vh,  g_wv2_h);
    cudaGetSymbolAddress((void**)&QKh, g_QKt_h);
    cudaGetSymbolAddress((void**)&Vh,  g_V2_h);
    cudaGetSymbolAddress((void**)&Ath, g_At_h);
    cudaGetSymbolAddress((void**)&bqk, g_bqk);
    cudaGetSymbolAddress((void**)&bv2, g_bv2);

    float* f_final = out;
    float* attn    = out + (size_t)3 * BATCH * C2 * NPIX;

    const size_t sX  = (size_t)NPIX * 2 * C2;  // per-batch Xt / QKt
    const size_t sQ  = (size_t)NPIX * C2;      // per-batch V2 / f_final
    const size_t sS  = (size_t)NPIX * NPIX;    // per-batch attn

    // 1) copies + transpose X
    pack_transpose_kernel<<<dim3(NPIX / 32, C2 / 32, BATCH * 2), dim3(32, 8)>>>(
        f_rgb, f_i, out);
    // 2) weight prep
    weights_prep_kernel<<<(unsigned)((size_t)C2 * 2 * C2 / 256), 256>>>(
        wq, wk, wv, bq, bk, bv);

    // 3a) fused Q+K projection: M=pix(4096), N=ch(4096)
    hgemm<0><<<dim3(2 * C2 / 256, NPIX / 128, BATCH), 256, GEMM_SMEM>>>(
        Xh, qkh, sX, 0, 2 * C2, 2 * C2, 2 * C2,
        QKh, 2 * C2, sX, 1.f, nullptr, bqk);

    // 3b) V2[ch][pix]: M=ch(2048), N=pix(4096)
    hgemm<0><<<dim3(NPIX / 256, C2 / 128, BATCH), 256, GEMM_SMEM>>>(
        vh, Xh, 0, sX, 2 * C2, 2 * C2, 2 * C2,
        Vh, NPIX, sQ, 1.f, bv2, nullptr);

    // 4) scores S[n][m] = Q.K/64: M=pix, N=pix
    hgemm<1><<<dim3(NPIX / 256, NPIX / 128, BATCH), 256, GEMM_SMEM>>>(
        QKh, QKh + C2, sX, sX, 2 * C2, 2 * C2, C2,
        attn, NPIX, sS, 1.f / 64.f, nullptr, nullptr);

    // 5) softmax (f32 out + fp16)
    softmax_kernel<<<BATCH * NPIX, 256>>>(attn, Ath);

    // 6) f_final[c][n]: M=ch(2048), N=pix(4096)
    hgemm<1><<<dim3(NPIX / 256, C2 / 128, BATCH), 256, GEMM_SMEM>>>(
        Vh, Ath, sQ, sS, NPIX, NPIX, NPIX,
        f_final, NPIX, sQ, 1.f, nullptr, nullptr);
}

// round 16
// speedup vs baseline: 1.0884x; 1.0884x over previous
#include <cuda_runtime.h>
#include <cuda_fp16.h>
#include <cstdint>

#define C2    2048
#define NPIX  4096
#define BATCH 2

typedef __half fp16;

// ---------------------------------------------------------------------------
// Static device scratch (no allocations anywhere)
// ---------------------------------------------------------------------------
__device__ fp16 g_Xt_h[(size_t)BATCH * NPIX * 2 * C2];   // [b][pix][4096 ch]
__device__ fp16 g_wqk_h[(size_t)2 * C2 * 2 * C2];        // [wq;wk] fused
__device__ fp16 g_wv2_h[(size_t)C2 * 2 * C2];            // folded V weights
__device__ float g_bqk[2 * C2];                          // [bq;bk]
__device__ float g_bv2[C2];
__device__ fp16 g_QKt_h[(size_t)BATCH * NPIX * 2 * C2];  // [b][pix][Q 0..2047|K 2048..4095]
__device__ fp16 g_V2_h[(size_t)BATCH * C2 * NPIX];       // [b][ch][pix]
__device__ fp16 g_At_h[(size_t)BATCH * NPIX * NPIX];     // attn fp16

// ---------------------------------------------------------------------------
// helpers
// ---------------------------------------------------------------------------
__device__ __forceinline__ uint32_t smem_u32(const void* p) {
    uint32_t a;
    asm("{ .reg .u64 t; cvta.to.shared.u64 t, %1; cvt.u32.u64 %0, t; }"
        : "=r"(a) : "l"(p));
    return a;
}
__device__ __forceinline__ uint32_t swz(uint32_t b) {       // 128B-row swizzle
    return b ^ ((b >> 3) & 0x70);
}
__device__ __forceinline__ void cp_async16(uint32_t dst, const void* src) {
    asm volatile("cp.async.cg.shared.global [%0], [%1], 16;\n"
                 :: "r"(dst), "l"(src) : "memory");
}
__device__ __forceinline__ void ldsm_x4(uint32_t* r, uint32_t addr) {
    asm volatile("ldmatrix.sync.aligned.m8n8.x4.shared.b16 {%0,%1,%2,%3}, [%4];"
                 : "=r"(r[0]), "=r"(r[1]), "=r"(r[2]), "=r"(r[3]) : "r"(addr));
}
__device__ __forceinline__ void mma16816(float* d, const uint32_t* a,
                                         const uint32_t* b) {
    asm volatile(
        "mma.sync.aligned.m16n8k16.row.col.f32.f16.f16.f32 "
        "{%0,%1,%2,%3}, {%4,%5,%6,%7}, {%8,%9}, {%0,%1,%2,%3};"
        : "+f"(d[0]), "+f"(d[1]), "+f"(d[2]), "+f"(d[3])
        : "r"(a[0]), "r"(a[1]), "r"(a[2]), "r"(a[3]), "r"(b[0]), "r"(b[1]));
}

// ---------------------------------------------------------------------------
// Pack + transpose: f_rgb/f_i -> fp32 output copies and Xt (fp16)
// ---------------------------------------------------------------------------
__global__ void pack_transpose_kernel(const float* __restrict__ frgb,
                                      const float* __restrict__ fi,
                                      float* __restrict__ out)
{
    __shared__ float tile[32][33];
    const int s = blockIdx.z & 1, b = blockIdx.z >> 1;
    const float* src = s ? fi : frgb;
    const int pix0 = blockIdx.x * 32, ch0 = blockIdx.y * 32;
    const size_t base = (size_t)b * C2 * NPIX;
    const size_t PER  = (size_t)BATCH * C2 * NPIX;
    const int tx = threadIdx.x, ty = threadIdx.y;
#pragma unroll
    for (int i = 0; i < 4; ++i) {
        const int ch = ch0 + ty + i * 8;
        const size_t idx = base + (size_t)ch * NPIX + pix0 + tx;
        float v = src[idx];
        out[PER * (1 + s) + idx] = v;          // f_rgb / f_i copy
        tile[ty + i * 8][tx] = v;
    }
    __syncthreads();
    const size_t xbase = (size_t)b * NPIX * (2 * C2) + (size_t)s * C2;
#pragma unroll
    for (int i = 0; i < 4; ++i) {
        const int pix = pix0 + ty + i * 8;
        float v = tile[tx][ty + i * 8];
        const size_t idx = xbase + (size_t)pix * (2 * C2) + ch0 + tx;
        g_Xt_h[idx] = __float2half_rn(v);
    }
}

// ---------------------------------------------------------------------------
// Weight prep: fused [wq;wk], fold wv, biases
// ---------------------------------------------------------------------------
__global__ void weights_prep_kernel(const float* __restrict__ wq,
                                    const float* __restrict__ wk,
                                    const float* __restrict__ wv,
                                    const float* __restrict__ bq,
                                    const float* __restrict__ bk,
                                    const float* __restrict__ bv)
{
    const size_t NW = (size_t)C2 * 2 * C2;
    size_t i = (size_t)blockIdx.x * blockDim.x + threadIdx.x;
    if (i < NW) {
        g_wqk_h[i]      = __float2half_rn(wq[i]);
        g_wqk_h[NW + i] = __float2half_rn(wk[i]);
        g_wv2_h[i]      = __float2half_rn(wv[i] + wv[i + NW]);
    }
    if (i < C2) {
        g_bqk[i]      = bq[i];
        g_bqk[C2 + i] = bk[i];
        g_bv2[i]      = bv[i] + bv[i + C2];
    }
}

// ---------------------------------------------------------------------------
// HMMA GEMM:  D[M,N] = alpha * A[M,K] @ B[N,K]^T (+bias)
// CTA tile 128x128, kTile 64, FOUR warps (warp tile 64x64, 2x2 grid),
// 128 threads, 3-slot cp.async ring (32KB/stage, 96KB smem) with
// wait_group 1, 2 CTAs/SM. 32-MMA distinct-accumulator streams per LDSM
// burst -> low smem-port load per MMA with retained co-residency.
// MODE 0: out fp16 row-major (+bias); MODE 1: out f32 row-major * alpha.
// ---------------------------------------------------------------------------
static constexpr int TILE16K   = 16384;          // one 128x64 fp16 tile
static constexpr int STAGE_B   = 2 * TILE16K;    // Ah, Bh = 32KB
static constexpr int GEMM_SMEM = 3 * STAGE_B + 128;

template<int MODE>
__global__ void __launch_bounds__(128, 2)
hgemm(const fp16* __restrict__ Ah, const fp16* __restrict__ Bh,
      size_t sAb, size_t sBb, int lda, int ldb, int K,
      void* __restrict__ out0v,
      int ldo, size_t sOb, float alpha,
      const float* __restrict__ bias_m, const float* __restrict__ bias_n)
{
    extern __shared__ __align__(128) char dsm[];
    const uint32_t smbase = (smem_u32(dsm) + 127u) & ~127u;

    const int tid  = threadIdx.x;
    const int lane = tid & 31, warp = tid >> 5;
    const int m0 = blockIdx.y * 128;
    const int n0 = blockIdx.x * 128;
    const int b  = blockIdx.z;
    Ah += sAb * b;
    Bh += sBb * b;

    const int wm = (warp >> 1) * 64;     // warp M offset (2 in M)
    const int wn = (warp & 1) * 64;      // warp N offset (2 in N)
    const int kcrot = (warp >> 1) * 2;   // kc phase stagger

    float acc[4][8][4];
#pragma unroll
    for (int i = 0; i < 4; ++i)
#pragma unroll
        for (int j = 0; j < 8; ++j)
#pragma unroll
            for (int q = 0; q < 4; ++q) acc[i][j][q] = 0.f;

    // ---- hoisted ldmatrix addressing ----
    const int arow = wm + (lane & 15);
    const int brow = wn + (lane & 15);
    const uint32_t hk  = (uint32_t)(lane >> 4);
    const uint32_t sxa = (uint32_t)(arow & 7);
    const uint32_t sxb = (uint32_t)(brow & 7);
    uint32_t colA[4], colB[4], aoff[4], boff[4];
#pragma unroll
    for (int kc = 0; kc < 4; ++kc) {
        const uint32_t kce = (uint32_t)((kc + kcrot) & 3);
        colA[kc] = (((kce * 2) + hk) ^ sxa) << 4;
        colB[kc] = (((kce * 2) + hk) ^ sxb) << 4;
    }
#pragma unroll
    for (int mi = 0; mi < 4; ++mi) aoff[mi] = (uint32_t)((arow + mi * 16) * 128);
#pragma unroll
    for (int g = 0; g < 4; ++g)    boff[g] = (uint32_t)((brow + g * 16) * 128);

    // ---- hoisted cp.async addressing (128 threads: 8 chunks per tile) ----
    const int r0t = tid >> 3;                         // row 0..15 (first chunk)
    const int c8  = (tid & 7) * 8;                    // fp16 col of 16B chunk
    const size_t gA0 = (size_t)(m0 + r0t) * lda + c8;
    const size_t gB0 = (size_t)(n0 + r0t) * ldb + c8;
    const size_t gstepA = (size_t)16 * lda;           // +16 rows per chunk
    const size_t gstepB = (size_t)16 * ldb;
    const uint32_t soff0 = swz((uint32_t)(r0t * 128 + (tid & 7) * 16));

    const int NK = K / 64;

    auto load_stage = [&](int kt, int slot) {
        if (kt < NK) {
            const uint32_t sb = smbase + (uint32_t)slot * STAGE_B;
            const int k0 = kt * 64;
            const fp16* pAh = Ah + gA0 + k0;
            const fp16* pBh = Bh + gB0 + k0;
#pragma unroll
            for (int j = 0; j < 8; ++j) {
                const uint32_t so = soff0 + (uint32_t)(j * 2048);
                cp_async16(sb + so,           pAh + (size_t)j * gstepA);
                cp_async16(sb + TILE16K + so, pBh + (size_t)j * gstepB);
            }
        }
        asm volatile("cp.async.commit_group;" ::: "memory");
    };

    load_stage(0, 0);
    load_stage(1, 1);
    int cur = 0, wr = 2;

    for (int kt = 0; kt < NK; ++kt) {
        asm volatile("cp.async.wait_group 1;" ::: "memory");
        __syncthreads();
        load_stage(kt + 2, wr);
        wr = (wr == 2) ? 0 : wr + 1;

        const uint32_t sb = smbase + (uint32_t)cur * STAGE_B;
        cur = (cur == 2) ? 0 : cur + 1;
        const uint32_t aH = sb;
        const uint32_t bH = sb + TILE16K;

#pragma unroll
        for (int kc = 0; kc < 4; ++kc) {
            const uint32_t cA = colA[kc], cB = colB[kc];
            uint32_t a1[4][4], b1[8][2], t[4];

#pragma unroll
            for (int mi = 0; mi < 4; ++mi)
                ldsm_x4(a1[mi], aH + aoff[mi] + cA);
#pragma unroll
            for (int g = 0; g < 4; ++g) {
                ldsm_x4(t, bH + boff[g] + cB);
                b1[2 * g][0]     = t[0]; b1[2 * g][1]     = t[2];
                b1[2 * g + 1][0] = t[1]; b1[2 * g + 1][1] = t[3];
            }
#pragma unroll
            for (int mi = 0; mi < 4; ++mi)
#pragma unroll
                for (int ni = 0; ni < 8; ++ni)
                    mma16816(acc[mi][ni], a1[mi], b1[ni]);
        }
    }

    // ------------------------------- epilogue ------------------------------
    const int r0 = m0 + wm + (lane >> 2);
    const int c0 = n0 + wn + (lane & 3) * 2;
#pragma unroll
    for (int mi = 0; mi < 4; ++mi) {
        const int rA = r0 + mi * 16, rB = rA + 8;
        float bmA = 0.f, bmB = 0.f;
        if (MODE == 0 && bias_m) { bmA = bias_m[rA]; bmB = bias_m[rB]; }
#pragma unroll
        for (int ni = 0; ni < 8; ++ni) {
            const int col = c0 + ni * 8;
            if (MODE == 1) {
                float* o = (float*)out0v + sOb * b;
                float2 u;
                u.x = acc[mi][ni][0] * alpha; u.y = acc[mi][ni][1] * alpha;
                *(float2*)(o + (size_t)rA * ldo + col) = u;
                u.x = acc[mi][ni][2] * alpha; u.y = acc[mi][ni][3] * alpha;
                *(float2*)(o + (size_t)rB * ldo + col) = u;
            } else {
                fp16* oh = (fp16*)out0v + sOb * b;
                float bn0 = 0.f, bn1 = 0.f;
                if (bias_n) { bn0 = bias_n[col]; bn1 = bias_n[col + 1]; }
                float v0 = acc[mi][ni][0] + bmA + bn0;
                float v1 = acc[mi][ni][1] + bmA + bn1;
                float v2 = acc[mi][ni][2] + bmB + bn0;
                float v3 = acc[mi][ni][3] + bmB + bn1;
                *(__half2*)(oh + (size_t)rA * ldo + col) =
                    __halves2half2(__float2half_rn(v0), __float2half_rn(v1));
                *(__half2*)(oh + (size_t)rB * ldo + col) =
                    __halves2half2(__float2half_rn(v2), __float2half_rn(v3));
            }
        }
    }
}

// ---------------------------------------------------------------------------
// Row softmax: f32 in/out on attn, plus fp16 for the final GEMM
// ---------------------------------------------------------------------------
__global__ void softmax_kernel(float* __restrict__ attn,
                               fp16* __restrict__ ah)
{
    const size_t roff = (size_t)blockIdx.x * NPIX;
    float* p = attn + roff;
    const int t = threadIdx.x;
    float v[16];
    float mx = -1e30f;
#pragma unroll
    for (int j = 0; j < 16; ++j) {
        v[j] = p[t + 256 * j];
        mx = fmaxf(mx, v[j]);
    }
    __shared__ float sred[8];
#pragma unroll
    for (int o = 16; o; o >>= 1)
        mx = fmaxf(mx, __shfl_xor_sync(0xffffffffu, mx, o));
    if ((t & 31) == 0) sred[t >> 5] = mx;
    __syncthreads();
    mx = sred[0];
#pragma unroll
    for (int k = 1; k < 8; ++k) mx = fmaxf(mx, sred[k]);

    float s = 0.f;
#pragma unroll
    for (int j = 0; j < 16; ++j) {
        v[j] = __expf(v[j] - mx);
        s += v[j];
    }
#pragma unroll
    for (int o = 16; o; o >>= 1)
        s += __shfl_xor_sync(0xffffffffu, s, o);
    __syncthreads();
    if ((t & 31) == 0) sred[t >> 5] = s;
    __syncthreads();
    s = 0.f;
#pragma unroll
    for (int k = 0; k < 8; ++k) s += sred[k];

    const float inv = 1.f / s;
#pragma unroll
    for (int j = 0; j < 16; ++j) {
        const int idx = t + 256 * j;
        float o = v[j] * inv;
        p[idx] = o;
        ah[roff + idx] = __float2half_rn(o);
    }
}

// ---------------------------------------------------------------------------
// kernel_launch (single stream — graph-capture safe)
// Inputs: f_rgb, f_i, wq, bq, wk, bk, wv, bv
// Output: [f_final | f_rgb | f_i | attn] fp32
// ---------------------------------------------------------------------------
extern "C" void kernel_launch(void* const* d_in, const int* in_sizes, int n_in,
                              void* d_out, int out_size)
{
    const float* f_rgb = (const float*)d_in[0];
    const float* f_i   = (const float*)d_in[1];
    const float* wq    = (const float*)d_in[2];
    const float* bq    = (const float*)d_in[3];
    const float* wk    = (const float*)d_in[4];
    const float* bk    = (const float*)d_in[5];
    const float* wv    = (const float*)d_in[6];
    const float* bv    = (const float*)d_in[7];
    float* out = (float*)d_out;

    cudaFuncSetAttribute(hgemm<0>, cudaFuncAttributeMaxDynamicSharedMemorySize, GEMM_SMEM);
    cudaFuncSetAttribute(hgemm<1>, cudaFuncAttributeMaxDynamicSharedMemorySize, GEMM_SMEM);

    fp16 *Xh, *qkh, *vh;
    fp16 *QKh, *Vh, *Ath;
    float *bqk, *bv2;
    cudaGetSymbolAddress((void**)&Xh,  g_Xt_h);
    cudaGetSymbolAddress((void**)&qkh, g_wqk_h);
    cudaGetSymbolAddress((void**)&vh,  g_wv2_h);
    cudaGetSymbolAddress((void**)&QKh, g_QKt_h);
    cudaGetSymbolAddress((void**)&Vh,  g_V2_h);
    cudaGetSymbolAddress((void**)&Ath, g_At_h);
    cudaGetSymbolAddress((void**)&bqk, g_bqk);
    cudaGetSymbolAddress((void**)&bv2, g_bv2);

    float* f_final = out;
    float* attn    = out + (size_t)3 * BATCH * C2 * NPIX;

    const size_t sX  = (size_t)NPIX * 2 * C2;  // per-batch Xt / QKt
    const size_t sQ  = (size_t)NPIX * C2;      // per-batch V2 / f_final
    const size_t sS  = (size_t)NPIX * NPIX;    // per-batch attn

    // 1) copies + transpose X
    pack_transpose_kernel<<<dim3(NPIX / 32, C2 / 32, BATCH * 2), dim3(32, 8)>>>(
        f_rgb, f_i, out);
    // 2) weight prep
    weights_prep_kernel<<<(unsigned)((size_t)C2 * 2 * C2 / 256), 256>>>(
        wq, wk, wv, bq, bk, bv);

    // 3a) fused Q+K projection
    hgemm<0><<<dim3(2 * C2 / 128, NPIX / 128, BATCH), 128, GEMM_SMEM>>>(
        Xh, qkh, sX, 0, 2 * C2, 2 * C2, 2 * C2,
        QKh, 2 * C2, sX, 1.f, nullptr, bqk);

    // 3b) V2[ch][pix]
    hgemm<0><<<dim3(NPIX / 128, C2 / 128, BATCH), 128, GEMM_SMEM>>>(
        vh, Xh, 0, sX, 2 * C2, 2 * C2, 2 * C2,
        Vh, NPIX, sQ, 1.f, bv2, nullptr);

    // 4) scores S[n][m] = Q.K/64
    hgemm<1><<<dim3(NPIX / 128, NPIX / 128, BATCH), 128, GEMM_SMEM>>>(
        QKh, QKh + C2, sX, sX, 2 * C2, 2 * C2, C2,
        attn, NPIX, sS, 1.f / 64.f, nullptr, nullptr);

    // 5) softmax (f32 out + fp16)
    softmax_kernel<<<BATCH * NPIX, 256>>>(attn, Ath);

    // 6) f_final[c][n] = sum_m V2[c,m] attn[n,m]
    hgemm<1><<<dim3(NPIX / 128, C2 / 128, BATCH), 128, GEMM_SMEM>>>(
        Vh, Ath, sQ, sS, NPIX, NPIX, NPIX,
        f_final, NPIX, sQ, 1.f, nullptr, nullptr);
}

// round 17
// speedup vs baseline: 1.0940x; 1.0051x over previous
#include <cuda_runtime.h>
#include <cuda_fp16.h>
#include <cstdint>

#define C2    2048
#define NPIX  4096
#define BATCH 2

typedef __half fp16;

// ---------------------------------------------------------------------------
// Static device scratch (no allocations anywhere)
// ---------------------------------------------------------------------------
__device__ fp16 g_Xt_h[(size_t)BATCH * NPIX * 2 * C2];   // [b][pix][4096 ch]
__device__ fp16 g_wqk_h[(size_t)2 * C2 * 2 * C2];        // [wq;wk] fused
__device__ fp16 g_wv2_h[(size_t)C2 * 2 * C2];            // folded V weights
__device__ float g_bqk[2 * C2];                          // [bq;bk]
__device__ float g_bv2[C2];
__device__ fp16 g_QKt_h[(size_t)BATCH * NPIX * 2 * C2];  // [b][pix][Q 0..2047|K 2048..4095]
__device__ fp16 g_V2_h[(size_t)BATCH * C2 * NPIX];       // [b][ch][pix]
__device__ fp16 g_At_h[(size_t)BATCH * NPIX * NPIX];     // attn fp16

// ---------------------------------------------------------------------------
// helpers
// ---------------------------------------------------------------------------
__device__ __forceinline__ uint32_t smem_u32(const void* p) {
    uint32_t a;
    asm("{ .reg .u64 t; cvta.to.shared.u64 t, %1; cvt.u32.u64 %0, t; }"
        : "=r"(a) : "l"(p));
    return a;
}
__device__ __forceinline__ uint32_t swz(uint32_t b) {       // 128B-row swizzle
    return b ^ ((b >> 3) & 0x70);
}
__device__ __forceinline__ void cp_async16(uint32_t dst, const void* src) {
    asm volatile("cp.async.cg.shared.global [%0], [%1], 16;\n"
                 :: "r"(dst), "l"(src) : "memory");
}
__device__ __forceinline__ void ldsm_x4(uint32_t* r, uint32_t addr) {
    asm volatile("ldmatrix.sync.aligned.m8n8.x4.shared.b16 {%0,%1,%2,%3}, [%4];"
                 : "=r"(r[0]), "=r"(r[1]), "=r"(r[2]), "=r"(r[3]) : "r"(addr));
}
__device__ __forceinline__ void mma16816(float* d, const uint32_t* a,
                                         const uint32_t* b) {
    asm volatile(
        "mma.sync.aligned.m16n8k16.row.col.f32.f16.f16.f32 "
        "{%0,%1,%2,%3}, {%4,%5,%6,%7}, {%8,%9}, {%0,%1,%2,%3};"
        : "+f"(d[0]), "+f"(d[1]), "+f"(d[2]), "+f"(d[3])
        : "r"(a[0]), "r"(a[1]), "r"(a[2]), "r"(a[3]), "r"(b[0]), "r"(b[1]));
}

// ---------------------------------------------------------------------------
// Pack + transpose: f_rgb/f_i -> fp32 output copies and Xt (fp16)
// ---------------------------------------------------------------------------
__global__ void pack_transpose_kernel(const float* __restrict__ frgb,
                                      const float* __restrict__ fi,
                                      float* __restrict__ out)
{
    __shared__ float tile[32][33];
    const int s = blockIdx.z & 1, b = blockIdx.z >> 1;
    const float* src = s ? fi : frgb;
    const int pix0 = blockIdx.x * 32, ch0 = blockIdx.y * 32;
    const size_t base = (size_t)b * C2 * NPIX;
    const size_t PER  = (size_t)BATCH * C2 * NPIX;
    const int tx = threadIdx.x, ty = threadIdx.y;
#pragma unroll
    for (int i = 0; i < 4; ++i) {
        const int ch = ch0 + ty + i * 8;
        const size_t idx = base + (size_t)ch * NPIX + pix0 + tx;
        float v = src[idx];
        out[PER * (1 + s) + idx] = v;          // f_rgb / f_i copy
        tile[ty + i * 8][tx] = v;
    }
    __syncthreads();
    const size_t xbase = (size_t)b * NPIX * (2 * C2) + (size_t)s * C2;
#pragma unroll
    for (int i = 0; i < 4; ++i) {
        const int pix = pix0 + ty + i * 8;
        float v = tile[tx][ty + i * 8];
        const size_t idx = xbase + (size_t)pix * (2 * C2) + ch0 + tx;
        g_Xt_h[idx] = __float2half_rn(v);
    }
}

// ---------------------------------------------------------------------------
// Weight prep: fused [wq;wk], fold wv, biases
// ---------------------------------------------------------------------------
__global__ void weights_prep_kernel(const float* __restrict__ wq,
                                    const float* __restrict__ wk,
                                    const float* __restrict__ wv,
                                    const float* __restrict__ bq,
                                    const float* __restrict__ bk,
                                    const float* __restrict__ bv)
{
    const size_t NW = (size_t)C2 * 2 * C2;
    size_t i = (size_t)blockIdx.x * blockDim.x + threadIdx.x;
    if (i < NW) {
        g_wqk_h[i]      = __float2half_rn(wq[i]);
        g_wqk_h[NW + i] = __float2half_rn(wk[i]);
        g_wv2_h[i]      = __float2half_rn(wv[i] + wv[i + NW]);
    }
    if (i < C2) {
        g_bqk[i]      = bq[i];
        g_bqk[C2 + i] = bk[i];
        g_bv2[i]      = bv[i] + bv[i + C2];
    }
}

// ---------------------------------------------------------------------------
// HMMA GEMM (R14 best config):  D[M,N] = alpha * A[M,K] @ B[N,K]^T (+bias)
// CTA tile 128x128, kTile 64, 8 warps (warp tile 64x32),
// 3-slot cp.async ring (32KB/stage) with wait_group 1, 2 CTAs/SM,
// kc order staggered per warp group.
// MODE 0: out fp16 row-major (+bias); MODE 1: out f32 row-major * alpha.
// ---------------------------------------------------------------------------
static constexpr int TILE16K   = 16384;          // one 128x64 fp16 tile
static constexpr int STAGE_B   = 2 * TILE16K;    // Ah, Bh = 32KB
static constexpr int GEMM_SMEM = 3 * STAGE_B + 128;

template<int MODE>
__global__ void __launch_bounds__(256, 2)
hgemm(const fp16* __restrict__ Ah, const fp16* __restrict__ Bh,
      size_t sAb, size_t sBb, int lda, int ldb, int K,
      void* __restrict__ out0v,
      int ldo, size_t sOb, float alpha,
      const float* __restrict__ bias_m, const float* __restrict__ bias_n)
{
    extern __shared__ __align__(128) char dsm[];
    const uint32_t smbase = (smem_u32(dsm) + 127u) & ~127u;

    const int tid  = threadIdx.x;
    const int lane = tid & 31, warp = tid >> 5;
    const int m0 = blockIdx.y * 128;
    const int n0 = blockIdx.x * 128;
    const int b  = blockIdx.z;
    Ah += sAb * b;
    Bh += sBb * b;

    const int wm = (warp >> 2) * 64;     // warp M offset
    const int wn = (warp & 3) * 32;      // warp N offset
    const int kcrot = (warp >> 2) * 2;   // kc phase rotation per warp group

    float acc[4][4][4];
#pragma unroll
    for (int i = 0; i < 4; ++i)
#pragma unroll
        for (int j = 0; j < 4; ++j)
#pragma unroll
            for (int q = 0; q < 4; ++q) acc[i][j][q] = 0.f;

    // ---- hoisted ldmatrix addressing (indexed by rotated kc) ----
    const int arow = wm + (lane & 15);
    const int brow = wn + (lane & 15);
    const uint32_t hk  = (uint32_t)(lane >> 4);
    const uint32_t sxa = (uint32_t)(arow & 7);
    const uint32_t sxb = (uint32_t)(brow & 7);
    uint32_t colA[4], colB[4], aoff[4];
#pragma unroll
    for (int kc = 0; kc < 4; ++kc) {
        const uint32_t kce = (uint32_t)((kc + kcrot) & 3);
        colA[kc] = (((kce * 2) + hk) ^ sxa) << 4;
        colB[kc] = (((kce * 2) + hk) ^ sxb) << 4;
    }
#pragma unroll
    for (int mi = 0; mi < 4; ++mi) aoff[mi] = (uint32_t)((arow + mi * 16) * 128);
    const uint32_t boff0 = (uint32_t)(brow * 128);
    const uint32_t boff1 = (uint32_t)((brow + 16) * 128);

    // ---- hoisted cp.async addressing ----
    const int r0t = tid >> 3;                         // row 0..31 (first chunk)
    const int c8  = (tid & 7) * 8;                    // fp16 col of 16B chunk
    const size_t gA0 = (size_t)(m0 + r0t) * lda + c8;
    const size_t gB0 = (size_t)(n0 + r0t) * ldb + c8;
    const size_t gstepA = (size_t)32 * lda;           // +32 rows per chunk
    const size_t gstepB = (size_t)32 * ldb;
    const uint32_t soff0 = swz((uint32_t)(r0t * 128 + (tid & 7) * 16));

    const int NK = K / 64;

    auto load_stage = [&](int kt, int slot) {
        if (kt < NK) {
            const uint32_t sb = smbase + (uint32_t)slot * STAGE_B;
            const int k0 = kt * 64;
            const fp16* pAh = Ah + gA0 + k0;
            const fp16* pBh = Bh + gB0 + k0;
#pragma unroll
            for (int j = 0; j < 4; ++j) {
                const uint32_t so = soff0 + (uint32_t)(j * 4096);
                cp_async16(sb + so,           pAh + (size_t)j * gstepA);
                cp_async16(sb + TILE16K + so, pBh + (size_t)j * gstepB);
            }
        }
        asm volatile("cp.async.commit_group;" ::: "memory");
    };

    load_stage(0, 0);
    load_stage(1, 1);
    int cur = 0, wr = 2;

    for (int kt = 0; kt < NK; ++kt) {
        asm volatile("cp.async.wait_group 1;" ::: "memory");
        __syncthreads();
        load_stage(kt + 2, wr);
        wr = (wr == 2) ? 0 : wr + 1;

        const uint32_t sb = smbase + (uint32_t)cur * STAGE_B;
        cur = (cur == 2) ? 0 : cur + 1;
        const uint32_t aH = sb;
        const uint32_t bH = sb + TILE16K;

#pragma unroll
        for (int kc = 0; kc < 4; ++kc) {
            const uint32_t cA = colA[kc], cB = colB[kc];
            uint32_t a1[4][4], b1[4][2], t[4];

#pragma unroll
            for (int mi = 0; mi < 4; ++mi)
                ldsm_x4(a1[mi], aH + aoff[mi] + cA);
            ldsm_x4(t, bH + boff0 + cB);
            b1[0][0] = t[0]; b1[0][1] = t[2]; b1[1][0] = t[1]; b1[1][1] = t[3];
            ldsm_x4(t, bH + boff1 + cB);
            b1[2][0] = t[0]; b1[2][1] = t[2]; b1[3][0] = t[1]; b1[3][1] = t[3];
#pragma unroll
            for (int mi = 0; mi < 4; ++mi)
#pragma unroll
                for (int ni = 0; ni < 4; ++ni)
                    mma16816(acc[mi][ni], a1[mi], b1[ni]);
        }
    }

    // ------------------------------- epilogue ------------------------------
    const int r0 = m0 + wm + (lane >> 2);
    const int c0 = n0 + wn + (lane & 3) * 2;
#pragma unroll
    for (int mi = 0; mi < 4; ++mi) {
        const int rA = r0 + mi * 16, rB = rA + 8;
        float bmA = 0.f, bmB = 0.f;
        if (MODE == 0 && bias_m) { bmA = bias_m[rA]; bmB = bias_m[rB]; }
#pragma unroll
        for (int ni = 0; ni < 4; ++ni) {
            const int col = c0 + ni * 8;
            if (MODE == 1) {
                float* o = (float*)out0v + sOb * b;
                float2 u;
                u.x = acc[mi][ni][0] * alpha; u.y = acc[mi][ni][1] * alpha;
                *(float2*)(o + (size_t)rA * ldo + col) = u;
                u.x = acc[mi][ni][2] * alpha; u.y = acc[mi][ni][3] * alpha;
                *(float2*)(o + (size_t)rB * ldo + col) = u;
            } else {
                fp16* oh = (fp16*)out0v + sOb * b;
                float bn0 = 0.f, bn1 = 0.f;
                if (bias_n) { bn0 = bias_n[col]; bn1 = bias_n[col + 1]; }
                float v0 = acc[mi][ni][0] + bmA + bn0;
                float v1 = acc[mi][ni][1] + bmA + bn1;
                float v2 = acc[mi][ni][2] + bmB + bn0;
                float v3 = acc[mi][ni][3] + bmB + bn1;
                *(__half2*)(oh + (size_t)rA * ldo + col) =
                    __halves2half2(__float2half_rn(v0), __float2half_rn(v1));
                *(__half2*)(oh + (size_t)rB * ldo + col) =
                    __halves2half2(__float2half_rn(v2), __float2half_rn(v3));
            }
        }
    }
}

// ---------------------------------------------------------------------------
// Row softmax (vectorized): float4 traffic on attn, half2 on the fp16 copy
// ---------------------------------------------------------------------------
__global__ void softmax_kernel(float* __restrict__ attn,
                               fp16* __restrict__ ah)
{
    const size_t roff = (size_t)blockIdx.x * NPIX;
    float4* p4 = reinterpret_cast<float4*>(attn + roff);
    __half2* a2 = reinterpret_cast<__half2*>(ah + roff);
    const int t = threadIdx.x;

    float4 v[4];
    float mx = -1e30f;
#pragma unroll
    for (int j = 0; j < 4; ++j) {
        v[j] = p4[t + 256 * j];
        mx = fmaxf(mx, fmaxf(fmaxf(v[j].x, v[j].y), fmaxf(v[j].z, v[j].w)));
    }
    __shared__ float sred[8];
#pragma unroll
    for (int o = 16; o; o >>= 1)
        mx = fmaxf(mx, __shfl_xor_sync(0xffffffffu, mx, o));
    if ((t & 31) == 0) sred[t >> 5] = mx;
    __syncthreads();
    mx = sred[0];
#pragma unroll
    for (int k = 1; k < 8; ++k) mx = fmaxf(mx, sred[k]);

    float s = 0.f;
#pragma unroll
    for (int j = 0; j < 4; ++j) {
        v[j].x = __expf(v[j].x - mx);
        v[j].y = __expf(v[j].y - mx);
        v[j].z = __expf(v[j].z - mx);
        v[j].w = __expf(v[j].w - mx);
        s += (v[j].x + v[j].y) + (v[j].z + v[j].w);
    }
#pragma unroll
    for (int o = 16; o; o >>= 1)
        s += __shfl_xor_sync(0xffffffffu, s, o);
    __syncthreads();
    if ((t & 31) == 0) sred[t >> 5] = s;
    __syncthreads();
    s = 0.f;
#pragma unroll
    for (int k = 0; k < 8; ++k) s += sred[k];

    const float inv = 1.f / s;
#pragma unroll
    for (int j = 0; j < 4; ++j) {
        float4 o;
        o.x = v[j].x * inv; o.y = v[j].y * inv;
        o.z = v[j].z * inv; o.w = v[j].w * inv;
        const int idx = t + 256 * j;
        p4[idx] = o;
        a2[2 * idx]     = __halves2half2(__float2half_rn(o.x), __float2half_rn(o.y));
        a2[2 * idx + 1] = __halves2half2(__float2half_rn(o.z), __float2half_rn(o.w));
    }
}

// ---------------------------------------------------------------------------
// kernel_launch (single stream — graph-capture safe)
// Inputs: f_rgb, f_i, wq, bq, wk, bk, wv, bv
// Output: [f_final | f_rgb | f_i | attn] fp32
// ---------------------------------------------------------------------------
extern "C" void kernel_launch(void* const* d_in, const int* in_sizes, int n_in,
                              void* d_out, int out_size)
{
    const float* f_rgb = (const float*)d_in[0];
    const float* f_i   = (const float*)d_in[1];
    const float* wq    = (const float*)d_in[2];
    const float* bq    = (const float*)d_in[3];
    const float* wk    = (const float*)d_in[4];
    const float* bk    = (const float*)d_in[5];
    const float* wv    = (const float*)d_in[6];
    const float* bv    = (const float*)d_in[7];
    float* out = (float*)d_out;

    cudaFuncSetAttribute(hgemm<0>, cudaFuncAttributeMaxDynamicSharedMemorySize, GEMM_SMEM);
    cudaFuncSetAttribute(hgemm<1>, cudaFuncAttributeMaxDynamicSharedMemorySize, GEMM_SMEM);

    fp16 *Xh, *qkh, *vh;
    fp16 *QKh, *Vh, *Ath;
    float *bqk, *bv2;
    cudaGetSymbolAddress((void**)&Xh,  g_Xt_h);
    cudaGetSymbolAddress((void**)&qkh, g_wqk_h);
    cudaGetSymbolAddress((void**)&vh,  g_wv2_h);
    cudaGetSymbolAddress((void**)&QKh, g_QKt_h);
    cudaGetSymbolAddress((void**)&Vh,  g_V2_h);
    cudaGetSymbolAddress((void**)&Ath, g_At_h);
    cudaGetSymbolAddress((void**)&bqk, g_bqk);
    cudaGetSymbolAddress((void**)&bv2, g_bv2);

    float* f_final = out;
    float* attn    = out + (size_t)3 * BATCH * C2 * NPIX;

    const size_t sX  = (size_t)NPIX * 2 * C2;  // per-batch Xt / QKt
    const size_t sQ  = (size_t)NPIX * C2;      // per-batch V2 / f_final
    const size_t sS  = (size_t)NPIX * NPIX;    // per-batch attn

    // 1) copies + transpose X
    pack_transpose_kernel<<<dim3(NPIX / 32, C2 / 32, BATCH * 2), dim3(32, 8)>>>(
        f_rgb, f_i, out);
    // 2) weight prep
    weights_prep_kernel<<<(unsigned)((size_t)C2 * 2 * C2 / 256), 256>>>(
        wq, wk, wv, bq, bk, bv);

    // 3a) fused Q+K projection
    hgemm<0><<<dim3(2 * C2 / 128, NPIX / 128, BATCH), 256, GEMM_SMEM>>>(
        Xh, qkh, sX, 0, 2 * C2, 2 * C2, 2 * C2,
        QKh, 2 * C2, sX, 1.f, nullptr, bqk);

    // 3b) V2[ch][pix]
    hgemm<0><<<dim3(NPIX / 128, C2 / 128, BATCH), 256, GEMM_SMEM>>>(
        vh, Xh, 0, sX, 2 * C2, 2 * C2, 2 * C2,
        Vh, NPIX, sQ, 1.f, bv2, nullptr);

    // 4) scores S[n][m] = Q.K/64
    hgemm<1><<<dim3(NPIX / 128, NPIX / 128, BATCH), 256, GEMM_SMEM>>>(
        QKh, QKh + C2, sX, sX, 2 * C2, 2 * C2, C2,
        attn, NPIX, sS, 1.f / 64.f, nullptr, nullptr);

    // 5) softmax (vectorized f32 out + fp16)
    softmax_kernel<<<BATCH * NPIX, 256>>>(attn, Ath);

    // 6) f_final[c][n] = sum_m V2[c,m] attn[n,m]
    hgemm<1><<<dim3(NPIX / 128, C2 / 128, BATCH), 256, GEMM_SMEM>>>(
        Vh, Ath, sQ, sS, NPIX, NPIX, NPIX,
        f_final, NPIX, sQ, 1.f, nullptr, nullptr);
}